// round 11
// baseline (speedup 1.0000x reference)
#include <cuda_runtime.h>
#include <math.h>

#define NB   16
#define NI   127
#define NN   16129      // 127*127
#define IMG  65536      // 256*256
#define TS   32
#define HL2  11
#define LT2  54         // TS + 2*HL2
#define LTN  2916       // LT2*LT2

typedef unsigned long long u64;

// ---------------- scratch (static device globals) ----------------------------
static __device__ float  g_x[NB * NN];
static __device__ float  g_r[NB * NN];
static __device__ float2 g_FA[NB * IMG];
static __device__ float2 g_FB[NB * IMG];   // also reused as float (real) buffer
static __device__ float2 g_Kc[NB * 98];    // composed 7x7 kernels: [49 fwd | 49 adj]
static __device__ float2 g_part[1024];

// ---------------- packed f32x2 helpers ---------------------------------------
__device__ __forceinline__ u64 pk2(float lo, float hi) {
    u64 r; asm("mov.b64 %0, {%1, %2};" : "=l"(r) : "f"(lo), "f"(hi)); return r;
}
__device__ __forceinline__ float2 upk(u64 v) {
    float2 r; asm("mov.b64 {%0, %1}, %2;" : "=f"(r.x), "=f"(r.y) : "l"(v)); return r;
}
__device__ __forceinline__ void cfma(u64& acc, u64 a, u64 b) {
    asm("fma.rn.f32x2 %0, %1, %2, %0;" : "+l"(acc) : "l"(a), "l"(b));
}

// ---------------- misc helpers ------------------------------------------------
__device__ __forceinline__ int get_K(const int* ep) {
    int ei = *ep;
    int e;
    if (ei > 0 && ei <= 1000000) {
        e = ei;
    } else {
        float ff = __int_as_float(ei);
        e = (ff >= 1.0f && ff <= 1000000.0f) ? (int)ff : 120;
    }
    int K = (e - 1) / 40 + 1;
    if (K > 10) K = 10;
    if (K < 1)  K = 1;
    return K;
}

// base-4 digit reversal of 8-bit index
__device__ __forceinline__ int dr4(int p) {
    return ((p & 3) << 6) | (((p >> 2) & 3) << 4) | (((p >> 4) & 3) << 2) | ((p >> 6) & 3);
}

__device__ __forceinline__ float2 cmulf(float2 a, float2 b) {
    return make_float2(a.x * b.x - a.y * b.y, a.x * b.y + a.y * b.x);
}

__device__ __forceinline__ void build_tw(float2* tw, int tid, float sign) {
    if (tid < 192) {
        float s, c;
        __sincosf(sign * 6.283185307179586f * (float)tid * (1.0f / 256.0f), &s, &c);
        tw[tid] = make_float2(c, s);
    }
}

// Radix-4 256-pt DIT FFT, input base-4 digit-reversed, output natural.
template <int STRIDE, int SGN>
__device__ __forceinline__ void fft256_r4(float2* s, const float2* tw, int t) {
#pragma unroll
    for (int st = 0; st < 4; ++st) {
        int L    = 1 << (2 * st);
        int k    = t & (L - 1);
        int g    = t >> (2 * st);
        int i0   = g * 4 * L + k;
        int step = 64 >> (2 * st);
        float2 a = s[i0 * STRIDE];
        float2 b = s[(i0 + L) * STRIDE];
        float2 c = s[(i0 + 2 * L) * STRIDE];
        float2 d = s[(i0 + 3 * L) * STRIDE];
        b = cmulf(b, tw[k * step]);
        c = cmulf(c, tw[2 * k * step]);
        d = cmulf(d, tw[3 * k * step]);
        float2 t0 = make_float2(a.x + c.x, a.y + c.y);
        float2 t1 = make_float2(a.x - c.x, a.y - c.y);
        float2 t2 = make_float2(b.x + d.x, b.y + d.y);
        float2 t3 = make_float2(b.x - d.x, b.y - d.y);
        float2 rot = make_float2(-(float)SGN * t3.y, (float)SGN * t3.x);
        s[i0 * STRIDE]           = make_float2(t0.x + t2.x, t0.y + t2.y);
        s[(i0 + L) * STRIDE]     = make_float2(t1.x + rot.x, t1.y + rot.y);
        s[(i0 + 2 * L) * STRIDE] = make_float2(t0.x - t2.x, t0.y - t2.y);
        s[(i0 + 3 * L) * STRIDE] = make_float2(t1.x - rot.x, t1.y - rot.y);
        __syncthreads();
    }
}

// ---------------- kernels ----------------------------------------------------
// One-time: compose the 3-conv stacks into per-sample 7x7 correlation kernels.
// Kf[m] = sum_{c1,c2} sum_{j+k+l=m} w3[0,c2][j] w2[c2,c1][k] w1[c1,0][l]
// Ka[m] = sum_{c1,c2} sum_{j+k+l=m} cj(w1[c2,0][jT]) cj(w2[c1,c2][kT]) cj(w3[0,c1][lT])
__global__ void __launch_bounds__(64)
compose_kernels(const float* __restrict__ w1r, const float* __restrict__ w1i,
                const float* __restrict__ w2r, const float* __restrict__ w2i,
                const float* __restrict__ w3r, const float* __restrict__ w3i) {
    __shared__ float s1r[36], s1i[36], s2r[144], s2i[144], s3r[36], s3i[36];
    int b = blockIdx.x;
    int t = threadIdx.x;
    if (t < 36) { s1r[t] = w1r[b * 36 + t]; s1i[t] = w1i[b * 36 + t]; }
    if (t < 36) { s3r[t] = w3r[b * 36 + t]; s3i[t] = w3i[b * 36 + t]; }
    for (int i = t; i < 144; i += 64) { s2r[i] = w2r[b * 144 + i]; s2i[i] = w2i[b * 144 + i]; }
    __syncthreads();
    if (t >= 49) return;
    int my = t / 7 - 3, mx = t % 7 - 3;
    float fr = 0.f, fi = 0.f, ar = 0.f, ai = 0.f;
    for (int c2 = 0; c2 < 4; ++c2)
    for (int c1 = 0; c1 < 4; ++c1)
    for (int j = 0; j < 9; ++j) {
        int jy = j / 3 - 1, jx = j % 3 - 1;
        for (int k = 0; k < 9; ++k) {
            int ky = k / 3 - 1, kx = k % 3 - 1;
            int ly = my - jy - ky, lx = mx - jx - kx;
            if (ly < -1 || ly > 1 || lx < -1 || lx > 1) continue;
            int l = (ly + 1) * 3 + (lx + 1);
            // forward: w3[0,c2][j] * w2[c2,c1][k] * w1[c1,0][l]
            {
                float xr = s3r[c2 * 9 + j],            xi = s3i[c2 * 9 + j];
                float yr = s2r[(c2 * 4 + c1) * 9 + k], yi = s2i[(c2 * 4 + c1) * 9 + k];
                float zr = s1r[c1 * 9 + l],            zi = s1i[c1 * 9 + l];
                float pr = xr * yr - xi * yi, pi = xr * yi + xi * yr;
                fr += pr * zr - pi * zi;
                fi += pr * zi + pi * zr;
            }
            // adjoint (tap-transposed, conjugated)
            {
                int jT = (j % 3) * 3 + j / 3;
                int kT = (k % 3) * 3 + k / 3;
                int lT = (l % 3) * 3 + l / 3;
                float xr = s1r[c2 * 9 + jT],            xi = -s1i[c2 * 9 + jT];
                float yr = s2r[(c1 * 4 + c2) * 9 + kT], yi = -s2i[(c1 * 4 + c2) * 9 + kT];
                float zr = s3r[c1 * 9 + lT],            zi = -s3i[c1 * 9 + lT];
                float pr = xr * yr - xi * yi, pi = xr * yi + xi * yr;
                ar += pr * zr - pi * zi;
                ai += pr * zi + pi * zr;
            }
        }
    }
    g_Kc[b * 98 + t]      = make_float2(fr, fi);
    g_Kc[b * 98 + 49 + t] = make_float2(ar, ai);
}

// Sweep-chunked Jacobi: 10 sweeps/launch on 54x54 tiles (halo 11), 512 threads.
__global__ void __launch_bounds__(512)
jacobi_tile(const float* __restrict__ f, const float* __restrict__ kA,
            const int* __restrict__ ep, int iter, int final_, int zero) {
    if (iter >= get_K(ep)) return;
    __shared__ float xs0[LTN], xs1[LTN], fs[LTN];
    int b  = blockIdx.z;
    int ox = blockIdx.x * TS - HL2;
    int oy = blockIdx.y * TS - HL2;
    int tid = threadIdx.x;
    const float* ka = kA + b * 9;
    float k0 = ka[0], k1 = ka[1], k2 = ka[2], k3 = ka[3], k4 = ka[4];
    float k5 = ka[5], k6 = ka[6], k7 = ka[7], k8 = ka[8];
    float tau = 0.5f / k4;

    int  iyk[6], ixk[6];
    bool okk[6], domk[6];
#pragma unroll
    for (int k = 0; k < 6; ++k) {
        int p = tid + k * 512;
        bool ok = p < LTN;
        int iy = 0, ix = 0;
        if (ok) { iy = p / LT2; ix = p - iy * LT2; }
        int gy = oy + iy, gx = ox + ix;
        bool dom = ok && ((unsigned)gy < 127u) && ((unsigned)gx < 127u);
        if (ok) {
            xs0[p] = (dom && !zero) ? g_x[b * NN + gy * 127 + gx] : 0.0f;
            fs[p]  = dom ? f[b * NN + gy * 127 + gx] : 0.0f;
        }
        iyk[k] = iy; ixk[k] = ix; okk[k] = ok; domk[k] = dom;
    }
    __syncthreads();

    float* cur = xs0;
    float* nxt = xs1;
#pragma unroll
    for (int s = 0; s < 10; ++s) {
        int a = s + 1;
#pragma unroll
        for (int k = 0; k < 6; ++k) {
            if (okk[k]) {
                int p = tid + k * 512;
                float nv = cur[p];
                int iy = iyk[k], ix = ixk[k];
                if (domk[k] && iy >= a && iy < LT2 - a && ix >= a && ix < LT2 - a) {
                    float ax = k0 * cur[p - LT2 - 1] + k1 * cur[p - LT2] + k2 * cur[p - LT2 + 1]
                             + k3 * cur[p - 1]       + k4 * cur[p]       + k5 * cur[p + 1]
                             + k6 * cur[p + LT2 - 1] + k7 * cur[p + LT2] + k8 * cur[p + LT2 + 1];
                    nv = cur[p] + tau * (fs[p] - ax);
                }
                nxt[p] = nv;
            }
        }
        __syncthreads();
        float* tsw = cur; cur = nxt; nxt = tsw;
    }

#pragma unroll
    for (int k = 0; k < 2; ++k) {
        int p2 = tid + k * 512;
        int py = p2 >> 5, px = p2 & 31;
        int iy = HL2 + py, ix = HL2 + px;
        int gy = oy + iy, gx = ox + ix;
        if (((unsigned)gy < 127u) && ((unsigned)gx < 127u)) {
            int i = iy * LT2 + ix;
            g_x[b * NN + gy * 127 + gx] = cur[i];
            if (final_) {
                float ax = k0 * cur[i - LT2 - 1] + k1 * cur[i - LT2] + k2 * cur[i - LT2 + 1]
                         + k3 * cur[i - 1]       + k4 * cur[i]       + k5 * cur[i + 1]
                         + k6 * cur[i + LT2 - 1] + k7 * cur[i + LT2] + k8 * cur[i + LT2 + 1];
                g_r[b * NN + gy * 127 + gx] = fs[i] - ax;
            }
        }
    }
}

// ifft2 pass 1 (odd symmetry): FFT rows 1..127; store only k=0..127.
__global__ void __launch_bounds__(512)
fft_row_expand(const int* __restrict__ ep, int iter) {
    if (iter >= get_K(ep)) return;
    __shared__ float2 s[8][256];
    __shared__ float2 tw[192];
    int b = blockIdx.y, t = threadIdx.x, ty = threadIdx.y;
    int y = blockIdx.x * 8 + ty + 1;
    bool ok = (y <= 127);
    build_tw(tw, ty * 64 + t, 1.0f);
    const float* rrow = g_r + (b * NN + (ok ? (y - 1) : 0) * 127);
#pragma unroll
    for (int k = 0; k < 4; ++k) {
        int p = t + k * 64;
        float v = 0.0f;
        if (ok) {
            if (p >= 1 && p <= 127)  v =  rrow[p - 1];
            else if (p >= 129)       v = -rrow[255 - p];
        }
        s[ty][dr4(p)] = make_float2(v, 0.0f);
    }
    __syncthreads();
    fft256_r4<1, 1>(s[ty], tw, t);
    if (ok) {
        float2* base = g_FA + (size_t)b * IMG;
#pragma unroll
        for (int k = 0; k < 2; ++k) {
            int kk = t + k * 64;
            float2 v0 = s[ty][kk];
            base[y * 256 + kk]         = v0;
            base[(256 - y) * 256 + kk] = make_float2(-v0.x, -v0.y);
            if (y == 1) {
                base[kk]             = make_float2(0.f, 0.f);
                base[128 * 256 + kk] = make_float2(0.f, 0.f);
            }
        }
    }
}

// ifft2 pass 2: columns 0..127; output purely REAL into g_FB (float view).
__global__ void __launch_bounds__(1024)
fft_col_inv(const int* __restrict__ ep, int iter) {
    if (iter >= get_K(ep)) return;
    __shared__ float2 s[256 * 16];
    __shared__ float2 tw[192];
    int b  = blockIdx.y;
    int tx = threadIdx.x, ty = threadIdx.y;     // 16 x 64
    int tid = ty * 16 + tx;
    int x = blockIdx.x * 16 + tx;               // 0..127
    build_tw(tw, tid, 1.0f);
#pragma unroll
    for (int k = 0; k < 4; ++k) {
        int r = ty + k * 64;
        s[dr4(r) * 16 + tx] = g_FA[(b * 256 + r) * 256 + x];
    }
    __syncthreads();
    fft256_r4<16, 1>(s + tx, tw, ty);
    const float sc = 1.0f / 65536.0f;
    float* FB = (float*)g_FB;
#pragma unroll
    for (int k = 0; k < 4; ++k) {
        int r = ty + k * 64;
        float val = s[r * 16 + tx].x * sc;
        int n2 = (r ^ 128);
        float* row = FB + (size_t)b * IMG + n2 * 256;
        if (x == 0) {
            row[128] = val;
            row[0]   = 0.0f;
        } else {
            row[x + 128] = val;
            row[128 - x] = -val;
        }
    }
}

// Composed 7x7 correlation. ADJ=false: real input (g_FB float view), *theta,
// write g_FA. ADJ=true: complex input g_FA, write g_FB.
template <bool ADJ>
__global__ void __launch_bounds__(512)
conv7(const float* __restrict__ inR, const float2* __restrict__ inC,
      float2* __restrict__ out,
      const float* __restrict__ thr, const float* __restrict__ thi,
      const int* __restrict__ ep, int iter) {
    if (iter >= get_K(ep)) return;
    __shared__ char smb[ADJ ? 38 * 38 * 8 : 38 * 38 * 4];
    __shared__ u64 K01[49], K23[49];
    float*  sr = (float*)smb;
    float2* sc = (float2*)smb;
    int b  = blockIdx.z;
    int ox = blockIdx.x * 32;
    int oy = blockIdx.y * 32;
    int tid = threadIdx.x;

    if (tid < 49) {
        float2 w = g_Kc[b * 98 + (ADJ ? 49 : 0) + tid];
        K01[tid] = pk2(w.x, w.y);
        K23[tid] = pk2(-w.y, w.x);
    }
    for (int i = tid; i < 38 * 38; i += 512) {
        int iy = i / 38, ix = i - (i / 38) * 38;
        int gy = oy - 3 + iy, gx = ox - 3 + ix;
        bool in = ((unsigned)gy < 256u) && ((unsigned)gx < 256u);
        if (!ADJ) sr[i] = in ? inR[(size_t)b * IMG + gy * 256 + gx] : 0.0f;
        else      sc[i] = in ? inC[(size_t)b * IMG + gy * 256 + gx] : make_float2(0.f, 0.f);
    }
    __syncthreads();

#pragma unroll
    for (int k = 0; k < 2; ++k) {
        int p = tid + k * 512;
        int py = p >> 5, px = p & 31;
        int base = py * 38 + px;
        u64 acc = 0;
#pragma unroll
        for (int t7 = 0; t7 < 49; ++t7) {
            int off = base + (t7 / 7) * 38 + (t7 % 7);
            if (!ADJ) {
                float v = sr[off];
                cfma(acc, pk2(v, v), K01[t7]);
            } else {
                float2 v = sc[off];
                cfma(acc, pk2(v.x, v.x), K01[t7]);
                cfma(acc, pk2(v.y, v.y), K23[t7]);
            }
        }
        int gidx = (oy + py) * 256 + (ox + px);
        float2 a = upk(acc);
        if (!ADJ) {
            float tr = thr[b * IMG + gidx], ti = thi[b * IMG + gidx];
            u64 r = 0;
            cfma(r, pk2(a.x, a.x), pk2(tr, ti));
            cfma(r, pk2(a.y, a.y), pk2(-ti, tr));
            a = upk(r);
        }
        out[(size_t)b * IMG + gidx] = a;
    }
}

// fft2 pass 1: ifftshift on read, forward FFT along x; store k=0..127 only.
__global__ void __launch_bounds__(512)
fft_row_fwd(const int* __restrict__ ep, int iter) {
    if (iter >= get_K(ep)) return;
    __shared__ float2 s[8][256];
    __shared__ float2 tw[192];
    int b = blockIdx.y, t = threadIdx.x, ty = threadIdx.y;
    int y = blockIdx.x * 8 + ty;
    build_tw(tw, ty * 64 + t, -1.0f);
    const float2* irow = g_FB + (b * 256 + (y ^ 128)) * 256;
#pragma unroll
    for (int k = 0; k < 4; ++k) {
        int p = t + k * 64;
        s[ty][dr4(p)] = irow[p ^ 128];
    }
    __syncthreads();
    fft256_r4<1, -1>(s[ty], tw, t);
    float2* orow = g_FA + (b * 256 + y) * 256;
    orow[t]      = s[ty][t];
    orow[t + 64] = s[ty][t + 64];
}

// fft2 pass 2: columns 0..127, crop 127x127, accumulate into x.
__global__ void __launch_bounds__(1024)
fft_col_fwd_accum(const int* __restrict__ ep, int iter) {
    if (iter >= get_K(ep)) return;
    __shared__ float2 s[256 * 16];
    __shared__ float2 tw[192];
    int b  = blockIdx.y;
    int tx = threadIdx.x, ty = threadIdx.y;     // 16 x 64
    int tid = ty * 16 + tx;
    int x = blockIdx.x * 16 + tx;
    build_tw(tw, tid, -1.0f);
#pragma unroll
    for (int k = 0; k < 4; ++k) {
        int r = ty + k * 64;
        s[dr4(r) * 16 + tx] = g_FA[(b * 256 + r) * 256 + x];
    }
    __syncthreads();
    fft256_r4<16, -1>(s + tx, tw, ty);
    if (x < 127) {
#pragma unroll
        for (int k = 0; k < 4; ++k) {
            int r = ty + k * 64;
            if (r < 127)
                g_x[b * NN + r * 127 + x] += s[r * 16 + tx].x;
        }
    }
}

// Residual norm.
__global__ void __launch_bounds__(256)
norm_partial(const float* __restrict__ f, const float* __restrict__ kA) {
    __shared__ float sr_s[256], sf_s[256];
    int b = blockIdx.y;
    int row = blockIdx.x * 2 + (threadIdx.x >> 7);
    int col = threadIdx.x & 127;
    float sr = 0.0f, sf = 0.0f;
    if (row < 127 && col < 127) {
        int p = row * 127 + col;
        const float* ka = kA + b * 9;
        const float* xb = g_x + b * NN;
        float s = 0.0f;
        if (row > 0) {
            if (col > 0)   s += ka[0] * xb[p - 128];
            s += ka[1] * xb[p - 127];
            if (col < 126) s += ka[2] * xb[p - 126];
        }
        if (col > 0)   s += ka[3] * xb[p - 1];
        s += ka[4] * xb[p];
        if (col < 126) s += ka[5] * xb[p + 1];
        if (row < 126) {
            if (col > 0)   s += ka[6] * xb[p + 126];
            s += ka[7] * xb[p + 127];
            if (col < 126) s += ka[8] * xb[p + 128];
        }
        float fv = f[b * NN + p];
        float rv = fv - s;
        sr = rv * rv;
        sf = fv * fv;
    }
    sr_s[threadIdx.x] = sr;
    sf_s[threadIdx.x] = sf;
    __syncthreads();
    for (int o = 128; o > 0; o >>= 1) {
        if (threadIdx.x < o) {
            sr_s[threadIdx.x] += sr_s[threadIdx.x + o];
            sf_s[threadIdx.x] += sf_s[threadIdx.x + o];
        }
        __syncthreads();
    }
    if (threadIdx.x == 0) g_part[b * 64 + blockIdx.x] = make_float2(sr_s[0], sf_s[0]);
}

__global__ void norm_final(float* __restrict__ out) {
    __shared__ float sr_s[256], sf_s[256];
    float sr = 0.0f, sf = 0.0f;
#pragma unroll
    for (int k = 0; k < 4; ++k) {
        float2 v = g_part[threadIdx.x + k * 256];
        sr += v.x; sf += v.y;
    }
    sr_s[threadIdx.x] = sr;
    sf_s[threadIdx.x] = sf;
    __syncthreads();
    for (int o = 128; o > 0; o >>= 1) {
        if (threadIdx.x < o) {
            sr_s[threadIdx.x] += sr_s[threadIdx.x + o];
            sf_s[threadIdx.x] += sf_s[threadIdx.x + o];
        }
        __syncthreads();
    }
    if (threadIdx.x == 0) out[0] = sqrtf(sr_s[0] / sf_s[0]);
}

// ---------------- launch ------------------------------------------------------
extern "C" void kernel_launch(void* const* d_in, const int* in_sizes, int n_in,
                              void* d_out, int out_size) {
    (void)in_sizes; (void)n_in; (void)out_size;
    const float* f   = (const float*)d_in[0];
    const float* kA  = (const float*)d_in[1];
    const float* w1r = (const float*)d_in[2];
    const float* w1i = (const float*)d_in[3];
    const float* w2r = (const float*)d_in[4];
    const float* w2i = (const float*)d_in[5];
    const float* w3r = (const float*)d_in[6];
    const float* w3i = (const float*)d_in[7];
    const float* thr = (const float*)d_in[8];
    const float* thi = (const float*)d_in[9];
    const int*   ep  = (const int*)d_in[10];
    float* out = (float*)d_out;

    void *pFA = nullptr, *pFB = nullptr;
    cudaGetSymbolAddress(&pFA, g_FA);
    cudaGetSymbolAddress(&pFB, g_FB);

    compose_kernels<<<NB, 64>>>(w1r, w1i, w2r, w2i, w3r, w3i);

    dim3 jg(4, 4, NB);
    for (int it = 0; it < 3; ++it) {
        jacobi_tile<<<jg, 512>>>(f, kA, ep, it, 0, it == 0 ? 1 : 0);
        jacobi_tile<<<jg, 512>>>(f, kA, ep, it, 1, 0);
        fft_row_expand<<<dim3(16, NB), dim3(64, 8)>>>(ep, it);
        fft_col_inv<<<dim3(8, NB), dim3(16, 64)>>>(ep, it);
        conv7<false><<<dim3(8, 8, NB), 512>>>(
            (const float*)pFB, nullptr, (float2*)pFA, thr, thi, ep, it);
        conv7<true><<<dim3(8, 8, NB), 512>>>(
            nullptr, (const float2*)pFA, (float2*)pFB, nullptr, nullptr, ep, it);
        fft_row_fwd<<<dim3(32, NB), dim3(64, 8)>>>(ep, it);
        fft_col_fwd_accum<<<dim3(8, NB), dim3(16, 64)>>>(ep, it);
    }

    norm_partial<<<dim3(64, NB), 256>>>(f, kA);
    norm_final<<<1, 256>>>(out);
}

// round 12
// speedup vs baseline: 2.1505x; 2.1505x over previous
#include <cuda_runtime.h>
#include <math.h>

#define NB   16
#define NI   127
#define NN   16129      // 127*127
#define IMG  65536      // 256*256
#define TS   32
#define HL2  11
#define LT2  54         // TS + 2*HL2
#define LTN  2916       // LT2*LT2

typedef unsigned long long u64;

// ---------------- scratch (static device globals) ----------------------------
static __device__ float  g_x[NB * NN];
static __device__ float  g_r[NB * NN];
static __device__ float2 g_FA[NB * IMG];
static __device__ float2 g_FB[NB * IMG];   // also reused as float (real) buffer
static __device__ float2 g_Kc[NB * 98];    // composed 7x7 kernels: [49 fwd | 49 adj]
static __device__ float2 g_part[1024];

// ---------------- misc helpers ------------------------------------------------
__device__ __forceinline__ int get_K(const int* ep) {
    int ei = *ep;
    int e;
    if (ei > 0 && ei <= 1000000) {
        e = ei;
    } else {
        float ff = __int_as_float(ei);
        e = (ff >= 1.0f && ff <= 1000000.0f) ? (int)ff : 120;
    }
    int K = (e - 1) / 40 + 1;
    if (K > 10) K = 10;
    if (K < 1)  K = 1;
    return K;
}

// base-4 digit reversal of 8-bit index
__device__ __forceinline__ int dr4(int p) {
    return ((p & 3) << 6) | (((p >> 2) & 3) << 4) | (((p >> 4) & 3) << 2) | ((p >> 6) & 3);
}

__device__ __forceinline__ float2 cmulf(float2 a, float2 b) {
    return make_float2(a.x * b.x - a.y * b.y, a.x * b.y + a.y * b.x);
}

__device__ __forceinline__ void build_tw(float2* tw, int tid, float sign) {
    if (tid < 192) {
        float s, c;
        __sincosf(sign * 6.283185307179586f * (float)tid * (1.0f / 256.0f), &s, &c);
        tw[tid] = make_float2(c, s);
    }
}

// Radix-4 256-pt DIT FFT, input base-4 digit-reversed, output natural.
template <int STRIDE, int SGN>
__device__ __forceinline__ void fft256_r4(float2* s, const float2* tw, int t) {
#pragma unroll
    for (int st = 0; st < 4; ++st) {
        int L    = 1 << (2 * st);
        int k    = t & (L - 1);
        int g    = t >> (2 * st);
        int i0   = g * 4 * L + k;
        int step = 64 >> (2 * st);
        float2 a = s[i0 * STRIDE];
        float2 b = s[(i0 + L) * STRIDE];
        float2 c = s[(i0 + 2 * L) * STRIDE];
        float2 d = s[(i0 + 3 * L) * STRIDE];
        b = cmulf(b, tw[k * step]);
        c = cmulf(c, tw[2 * k * step]);
        d = cmulf(d, tw[3 * k * step]);
        float2 t0 = make_float2(a.x + c.x, a.y + c.y);
        float2 t1 = make_float2(a.x - c.x, a.y - c.y);
        float2 t2 = make_float2(b.x + d.x, b.y + d.y);
        float2 t3 = make_float2(b.x - d.x, b.y - d.y);
        float2 rot = make_float2(-(float)SGN * t3.y, (float)SGN * t3.x);
        s[i0 * STRIDE]           = make_float2(t0.x + t2.x, t0.y + t2.y);
        s[(i0 + L) * STRIDE]     = make_float2(t1.x + rot.x, t1.y + rot.y);
        s[(i0 + 2 * L) * STRIDE] = make_float2(t0.x - t2.x, t0.y - t2.y);
        s[(i0 + 3 * L) * STRIDE] = make_float2(t1.x - rot.x, t1.y - rot.y);
        __syncthreads();
    }
}

// ---------------- kernels ----------------------------------------------------
// One-time: compose the 3-conv stacks into per-sample 7x7 correlation kernels.
__global__ void __launch_bounds__(64)
compose_kernels(const float* __restrict__ w1r, const float* __restrict__ w1i,
                const float* __restrict__ w2r, const float* __restrict__ w2i,
                const float* __restrict__ w3r, const float* __restrict__ w3i) {
    __shared__ float s1r[36], s1i[36], s2r[144], s2i[144], s3r[36], s3i[36];
    int b = blockIdx.x;
    int t = threadIdx.x;
    if (t < 36) { s1r[t] = w1r[b * 36 + t]; s1i[t] = w1i[b * 36 + t]; }
    if (t < 36) { s3r[t] = w3r[b * 36 + t]; s3i[t] = w3i[b * 36 + t]; }
    for (int i = t; i < 144; i += 64) { s2r[i] = w2r[b * 144 + i]; s2i[i] = w2i[b * 144 + i]; }
    __syncthreads();
    if (t >= 49) return;
    int my = t / 7 - 3, mx = t % 7 - 3;
    float fr = 0.f, fi = 0.f, ar = 0.f, ai = 0.f;
    for (int c2 = 0; c2 < 4; ++c2)
    for (int c1 = 0; c1 < 4; ++c1)
    for (int j = 0; j < 9; ++j) {
        int jy = j / 3 - 1, jx = j % 3 - 1;
        for (int k = 0; k < 9; ++k) {
            int ky = k / 3 - 1, kx = k % 3 - 1;
            int ly = my - jy - ky, lx = mx - jx - kx;
            if (ly < -1 || ly > 1 || lx < -1 || lx > 1) continue;
            int l = (ly + 1) * 3 + (lx + 1);
            {
                float xr = s3r[c2 * 9 + j],            xi = s3i[c2 * 9 + j];
                float yr = s2r[(c2 * 4 + c1) * 9 + k], yi = s2i[(c2 * 4 + c1) * 9 + k];
                float zr = s1r[c1 * 9 + l],            zi = s1i[c1 * 9 + l];
                float pr = xr * yr - xi * yi, pi = xr * yi + xi * yr;
                fr += pr * zr - pi * zi;
                fi += pr * zi + pi * zr;
            }
            {
                int jT = (j % 3) * 3 + j / 3;
                int kT = (k % 3) * 3 + k / 3;
                int lT = (l % 3) * 3 + l / 3;
                float xr = s1r[c2 * 9 + jT],            xi = -s1i[c2 * 9 + jT];
                float yr = s2r[(c1 * 4 + c2) * 9 + kT], yi = -s2i[(c1 * 4 + c2) * 9 + kT];
                float zr = s3r[c1 * 9 + lT],            zi = -s3i[c1 * 9 + lT];
                float pr = xr * yr - xi * yi, pi = xr * yi + xi * yr;
                ar += pr * zr - pi * zi;
                ai += pr * zi + pi * zr;
            }
        }
    }
    g_Kc[b * 98 + t]      = make_float2(fr, fi);
    g_Kc[b * 98 + 49 + t] = make_float2(ar, ai);
}

// Sweep-chunked Jacobi: 10 sweeps/launch on 54x54 tiles (halo 11), 512 threads.
__global__ void __launch_bounds__(512)
jacobi_tile(const float* __restrict__ f, const float* __restrict__ kA,
            const int* __restrict__ ep, int iter, int final_, int zero) {
    if (iter >= get_K(ep)) return;
    __shared__ float xs0[LTN], xs1[LTN], fs[LTN];
    int b  = blockIdx.z;
    int ox = blockIdx.x * TS - HL2;
    int oy = blockIdx.y * TS - HL2;
    int tid = threadIdx.x;
    const float* ka = kA + b * 9;
    float k0 = ka[0], k1 = ka[1], k2 = ka[2], k3 = ka[3], k4 = ka[4];
    float k5 = ka[5], k6 = ka[6], k7 = ka[7], k8 = ka[8];
    float tau = 0.5f / k4;

    int  iyk[6], ixk[6];
    bool okk[6], domk[6];
#pragma unroll
    for (int k = 0; k < 6; ++k) {
        int p = tid + k * 512;
        bool ok = p < LTN;
        int iy = 0, ix = 0;
        if (ok) { iy = p / LT2; ix = p - iy * LT2; }
        int gy = oy + iy, gx = ox + ix;
        bool dom = ok && ((unsigned)gy < 127u) && ((unsigned)gx < 127u);
        if (ok) {
            xs0[p] = (dom && !zero) ? g_x[b * NN + gy * 127 + gx] : 0.0f;
            fs[p]  = dom ? f[b * NN + gy * 127 + gx] : 0.0f;
        }
        iyk[k] = iy; ixk[k] = ix; okk[k] = ok; domk[k] = dom;
    }
    __syncthreads();

    float* cur = xs0;
    float* nxt = xs1;
#pragma unroll
    for (int s = 0; s < 10; ++s) {
        int a = s + 1;
#pragma unroll
        for (int k = 0; k < 6; ++k) {
            if (okk[k]) {
                int p = tid + k * 512;
                float nv = cur[p];
                int iy = iyk[k], ix = ixk[k];
                if (domk[k] && iy >= a && iy < LT2 - a && ix >= a && ix < LT2 - a) {
                    float ax = k0 * cur[p - LT2 - 1] + k1 * cur[p - LT2] + k2 * cur[p - LT2 + 1]
                             + k3 * cur[p - 1]       + k4 * cur[p]       + k5 * cur[p + 1]
                             + k6 * cur[p + LT2 - 1] + k7 * cur[p + LT2] + k8 * cur[p + LT2 + 1];
                    nv = cur[p] + tau * (fs[p] - ax);
                }
                nxt[p] = nv;
            }
        }
        __syncthreads();
        float* tsw = cur; cur = nxt; nxt = tsw;
    }

#pragma unroll
    for (int k = 0; k < 2; ++k) {
        int p2 = tid + k * 512;
        int py = p2 >> 5, px = p2 & 31;
        int iy = HL2 + py, ix = HL2 + px;
        int gy = oy + iy, gx = ox + ix;
        if (((unsigned)gy < 127u) && ((unsigned)gx < 127u)) {
            int i = iy * LT2 + ix;
            g_x[b * NN + gy * 127 + gx] = cur[i];
            if (final_) {
                float ax = k0 * cur[i - LT2 - 1] + k1 * cur[i - LT2] + k2 * cur[i - LT2 + 1]
                         + k3 * cur[i - 1]       + k4 * cur[i]       + k5 * cur[i + 1]
                         + k6 * cur[i + LT2 - 1] + k7 * cur[i + LT2] + k8 * cur[i + LT2 + 1];
                g_r[b * NN + gy * 127 + gx] = fs[i] - ax;
            }
        }
    }
}

// ifft2 pass 1 (odd symmetry): FFT rows 1..127; store only k=0..127.
__global__ void __launch_bounds__(512)
fft_row_expand(const int* __restrict__ ep, int iter) {
    if (iter >= get_K(ep)) return;
    __shared__ float2 s[8][256];
    __shared__ float2 tw[192];
    int b = blockIdx.y, t = threadIdx.x, ty = threadIdx.y;
    int y = blockIdx.x * 8 + ty + 1;
    bool ok = (y <= 127);
    build_tw(tw, ty * 64 + t, 1.0f);
    const float* rrow = g_r + (b * NN + (ok ? (y - 1) : 0) * 127);
#pragma unroll
    for (int k = 0; k < 4; ++k) {
        int p = t + k * 64;
        float v = 0.0f;
        if (ok) {
            if (p >= 1 && p <= 127)  v =  rrow[p - 1];
            else if (p >= 129)       v = -rrow[255 - p];
        }
        s[ty][dr4(p)] = make_float2(v, 0.0f);
    }
    __syncthreads();
    fft256_r4<1, 1>(s[ty], tw, t);
    if (ok) {
        float2* base = g_FA + (size_t)b * IMG;
#pragma unroll
        for (int k = 0; k < 2; ++k) {
            int kk = t + k * 64;
            float2 v0 = s[ty][kk];
            base[y * 256 + kk]         = v0;
            base[(256 - y) * 256 + kk] = make_float2(-v0.x, -v0.y);
            if (y == 1) {
                base[kk]             = make_float2(0.f, 0.f);
                base[128 * 256 + kk] = make_float2(0.f, 0.f);
            }
        }
    }
}

// ifft2 pass 2: columns 0..127; output purely REAL into g_FB (float view).
__global__ void __launch_bounds__(1024)
fft_col_inv(const int* __restrict__ ep, int iter) {
    if (iter >= get_K(ep)) return;
    __shared__ float2 s[256 * 16];
    __shared__ float2 tw[192];
    int b  = blockIdx.y;
    int tx = threadIdx.x, ty = threadIdx.y;     // 16 x 64
    int tid = ty * 16 + tx;
    int x = blockIdx.x * 16 + tx;               // 0..127
    build_tw(tw, tid, 1.0f);
#pragma unroll
    for (int k = 0; k < 4; ++k) {
        int r = ty + k * 64;
        s[dr4(r) * 16 + tx] = g_FA[(b * 256 + r) * 256 + x];
    }
    __syncthreads();
    fft256_r4<16, 1>(s + tx, tw, ty);
    const float sc = 1.0f / 65536.0f;
    float* FB = (float*)g_FB;
#pragma unroll
    for (int k = 0; k < 4; ++k) {
        int r = ty + k * 64;
        float val = s[r * 16 + tx].x * sc;
        int n2 = (r ^ 128);
        float* row = FB + (size_t)b * IMG + n2 * 256;
        if (x == 0) {
            row[128] = val;
            row[0]   = 0.0f;
        } else {
            row[x + 128] = val;
            row[128 - x] = -val;
        }
    }
}

// Composed 7x7 correlation, scalar FFMA, 256 threads x 4 px, independent chains.
// ADJ=false: real input (g_FB float view), *theta, write g_FA.
// ADJ=true : complex input g_FA, write g_FB.
template <bool ADJ>
__global__ void __launch_bounds__(256)
conv7(const float* __restrict__ inR, const float2* __restrict__ inC,
      float2* __restrict__ out,
      const float* __restrict__ thr, const float* __restrict__ thi,
      const int* __restrict__ ep, int iter) {
    if (iter >= get_K(ep)) return;
    __shared__ char smb[ADJ ? 38 * 38 * 8 : 38 * 38 * 4];
    __shared__ float Kr[49], Ki[49];
    float*  sr = (float*)smb;
    float2* sc = (float2*)smb;
    int b  = blockIdx.z;
    int ox = blockIdx.x * 32;
    int oy = blockIdx.y * 32;
    int tid = threadIdx.x;

    if (tid < 49) {
        float2 w = g_Kc[b * 98 + (ADJ ? 49 : 0) + tid];
        Kr[tid] = w.x;
        Ki[tid] = w.y;
    }
    for (int i = tid; i < 38 * 38; i += 256) {
        int iy = i / 38, ix = i - iy * 38;
        int gy = oy - 3 + iy, gx = ox - 3 + ix;
        bool in = ((unsigned)gy < 256u) && ((unsigned)gx < 256u);
        if (!ADJ) sr[i] = in ? inR[(size_t)b * IMG + gy * 256 + gx] : 0.0f;
        else      sc[i] = in ? inC[(size_t)b * IMG + gy * 256 + gx] : make_float2(0.f, 0.f);
    }
    __syncthreads();

    // 4 px per thread: px p = tid + k*256 (rows 8k..8k+7 strip-major)
    float aR[4] = {0.f, 0.f, 0.f, 0.f};
    float aI[4] = {0.f, 0.f, 0.f, 0.f};
    int base[4];
#pragma unroll
    for (int k = 0; k < 4; ++k) {
        int p = tid + k * 256;
        base[k] = (p >> 5) * 38 + (p & 31);
    }

    for (int dy = 0; dy < 7; ++dy) {
        int rowo = dy * 38;
#pragma unroll
        for (int dx = 0; dx < 7; ++dx) {
            float wr = Kr[dy * 7 + dx];
            float wi = Ki[dy * 7 + dx];
            int off = rowo + dx;
#pragma unroll
            for (int k = 0; k < 4; ++k) {
                if (!ADJ) {
                    float v = sr[base[k] + off];
                    aR[k] = fmaf(v, wr, aR[k]);
                    aI[k] = fmaf(v, wi, aI[k]);
                } else {
                    float2 v = sc[base[k] + off];
                    aR[k] = fmaf(v.x, wr, fmaf(-v.y, wi, aR[k]));
                    aI[k] = fmaf(v.x, wi, fmaf(v.y, wr, aI[k]));
                }
            }
        }
    }

#pragma unroll
    for (int k = 0; k < 4; ++k) {
        int p = tid + k * 256;
        int gidx = (oy + (p >> 5)) * 256 + (ox + (p & 31));
        float rr = aR[k], ii = aI[k];
        if (!ADJ) {
            float tr = thr[b * IMG + gidx], ti = thi[b * IMG + gidx];
            float nr = rr * tr - ii * ti;
            float ni = rr * ti + ii * tr;
            rr = nr; ii = ni;
        }
        out[(size_t)b * IMG + gidx] = make_float2(rr, ii);
    }
}

// fft2 pass 1: ifftshift on read, forward FFT along x; store k=0..127 only.
__global__ void __launch_bounds__(512)
fft_row_fwd(const int* __restrict__ ep, int iter) {
    if (iter >= get_K(ep)) return;
    __shared__ float2 s[8][256];
    __shared__ float2 tw[192];
    int b = blockIdx.y, t = threadIdx.x, ty = threadIdx.y;
    int y = blockIdx.x * 8 + ty;
    build_tw(tw, ty * 64 + t, -1.0f);
    const float2* irow = g_FB + (b * 256 + (y ^ 128)) * 256;
#pragma unroll
    for (int k = 0; k < 4; ++k) {
        int p = t + k * 64;
        s[ty][dr4(p)] = irow[p ^ 128];
    }
    __syncthreads();
    fft256_r4<1, -1>(s[ty], tw, t);
    float2* orow = g_FA + (b * 256 + y) * 256;
    orow[t]      = s[ty][t];
    orow[t + 64] = s[ty][t + 64];
}

// fft2 pass 2: columns 0..127, crop 127x127, accumulate into x.
__global__ void __launch_bounds__(1024)
fft_col_fwd_accum(const int* __restrict__ ep, int iter) {
    if (iter >= get_K(ep)) return;
    __shared__ float2 s[256 * 16];
    __shared__ float2 tw[192];
    int b  = blockIdx.y;
    int tx = threadIdx.x, ty = threadIdx.y;     // 16 x 64
    int tid = ty * 16 + tx;
    int x = blockIdx.x * 16 + tx;
    build_tw(tw, tid, -1.0f);
#pragma unroll
    for (int k = 0; k < 4; ++k) {
        int r = ty + k * 64;
        s[dr4(r) * 16 + tx] = g_FA[(b * 256 + r) * 256 + x];
    }
    __syncthreads();
    fft256_r4<16, -1>(s + tx, tw, ty);
    if (x < 127) {
#pragma unroll
        for (int k = 0; k < 4; ++k) {
            int r = ty + k * 64;
            if (r < 127)
                g_x[b * NN + r * 127 + x] += s[r * 16 + tx].x;
        }
    }
}

// Residual norm.
__global__ void __launch_bounds__(256)
norm_partial(const float* __restrict__ f, const float* __restrict__ kA) {
    __shared__ float sr_s[256], sf_s[256];
    int b = blockIdx.y;
    int row = blockIdx.x * 2 + (threadIdx.x >> 7);
    int col = threadIdx.x & 127;
    float sr = 0.0f, sf = 0.0f;
    if (row < 127 && col < 127) {
        int p = row * 127 + col;
        const float* ka = kA + b * 9;
        const float* xb = g_x + b * NN;
        float s = 0.0f;
        if (row > 0) {
            if (col > 0)   s += ka[0] * xb[p - 128];
            s += ka[1] * xb[p - 127];
            if (col < 126) s += ka[2] * xb[p - 126];
        }
        if (col > 0)   s += ka[3] * xb[p - 1];
        s += ka[4] * xb[p];
        if (col < 126) s += ka[5] * xb[p + 1];
        if (row < 126) {
            if (col > 0)   s += ka[6] * xb[p + 126];
            s += ka[7] * xb[p + 127];
            if (col < 126) s += ka[8] * xb[p + 128];
        }
        float fv = f[b * NN + p];
        float rv = fv - s;
        sr = rv * rv;
        sf = fv * fv;
    }
    sr_s[threadIdx.x] = sr;
    sf_s[threadIdx.x] = sf;
    __syncthreads();
    for (int o = 128; o > 0; o >>= 1) {
        if (threadIdx.x < o) {
            sr_s[threadIdx.x] += sr_s[threadIdx.x + o];
            sf_s[threadIdx.x] += sf_s[threadIdx.x + o];
        }
        __syncthreads();
    }
    if (threadIdx.x == 0) g_part[b * 64 + blockIdx.x] = make_float2(sr_s[0], sf_s[0]);
}

__global__ void norm_final(float* __restrict__ out) {
    __shared__ float sr_s[256], sf_s[256];
    float sr = 0.0f, sf = 0.0f;
#pragma unroll
    for (int k = 0; k < 4; ++k) {
        float2 v = g_part[threadIdx.x + k * 256];
        sr += v.x; sf += v.y;
    }
    sr_s[threadIdx.x] = sr;
    sf_s[threadIdx.x] = sf;
    __syncthreads();
    for (int o = 128; o > 0; o >>= 1) {
        if (threadIdx.x < o) {
            sr_s[threadIdx.x] += sr_s[threadIdx.x + o];
            sf_s[threadIdx.x] += sf_s[threadIdx.x + o];
        }
        __syncthreads();
    }
    if (threadIdx.x == 0) out[0] = sqrtf(sr_s[0] / sf_s[0]);
}

// ---------------- launch ------------------------------------------------------
extern "C" void kernel_launch(void* const* d_in, const int* in_sizes, int n_in,
                              void* d_out, int out_size) {
    (void)in_sizes; (void)n_in; (void)out_size;
    const float* f   = (const float*)d_in[0];
    const float* kA  = (const float*)d_in[1];
    const float* w1r = (const float*)d_in[2];
    const float* w1i = (const float*)d_in[3];
    const float* w2r = (const float*)d_in[4];
    const float* w2i = (const float*)d_in[5];
    const float* w3r = (const float*)d_in[6];
    const float* w3i = (const float*)d_in[7];
    const float* thr = (const float*)d_in[8];
    const float* thi = (const float*)d_in[9];
    const int*   ep  = (const int*)d_in[10];
    float* out = (float*)d_out;

    void *pFA = nullptr, *pFB = nullptr;
    cudaGetSymbolAddress(&pFA, g_FA);
    cudaGetSymbolAddress(&pFB, g_FB);

    compose_kernels<<<NB, 64>>>(w1r, w1i, w2r, w2i, w3r, w3i);

    dim3 jg(4, 4, NB);
    for (int it = 0; it < 3; ++it) {
        jacobi_tile<<<jg, 512>>>(f, kA, ep, it, 0, it == 0 ? 1 : 0);
        jacobi_tile<<<jg, 512>>>(f, kA, ep, it, 1, 0);
        fft_row_expand<<<dim3(16, NB), dim3(64, 8)>>>(ep, it);
        fft_col_inv<<<dim3(8, NB), dim3(16, 64)>>>(ep, it);
        conv7<false><<<dim3(8, 8, NB), 256>>>(
            (const float*)pFB, nullptr, (float2*)pFA, thr, thi, ep, it);
        conv7<true><<<dim3(8, 8, NB), 256>>>(
            nullptr, (const float2*)pFA, (float2*)pFB, nullptr, nullptr, ep, it);
        fft_row_fwd<<<dim3(32, NB), dim3(64, 8)>>>(ep, it);
        fft_col_fwd_accum<<<dim3(8, NB), dim3(16, 64)>>>(ep, it);
    }

    norm_partial<<<dim3(64, NB), 256>>>(f, kA);
    norm_final<<<1, 256>>>(out);
}